// round 12
// baseline (speedup 1.0000x reference)
#include <cuda_runtime.h>

#define NB 16
#define NN 1024
#define ND 1024
#define NU 512

// Scratch (device globals — no allocation allowed).
// g_vh/g_vm are accumulators: zero at module load, re-zeroed at the end of
// k_outer each call, so every kernel_launch sees them zeroed.
__device__ float g_vh[ND];
__device__ float g_vm[ND];
__device__ float g_c;                 // w_out.(b_h+b_m) + b_out
__device__ float g_sH[NB * NN];       // c folded in by k_rowdots
__device__ float g_sM[NB * NN];

// ---------------------------------------------------------------------------
// Kernel 1: fold the U dimension (R9 geometry, measured 5.2us standalone).
// Triggers programmatic launch of k_rowdots at entry so rowdots' x-loads
// overlap the fold.
// ---------------------------------------------------------------------------
__global__ void k_fold(const float* __restrict__ W_h, const float* __restrict__ W_m,
                       const float* __restrict__ w_out, const float* __restrict__ b_h,
                       const float* __restrict__ b_m, const float* __restrict__ b_out) {
    cudaTriggerProgrammaticLaunchCompletion();
    const int tid = threadIdx.x;

    if (blockIdx.x < 256) {
        const bool is_h = blockIdx.x < 128;
        const int t = is_h ? blockIdx.x : blockIdx.x - 128;
        const int utile = t >> 3;            // 0..15
        const int dtile = t & 7;             // 0..7
        const int wgrp  = tid >> 5;          // 0..7
        const int d4    = dtile * 32 + (tid & 31);

        const float4* W4 = reinterpret_cast<const float4*>(is_h ? W_h : W_m);
        const int u_base = utile * 32 + wgrp;

        float4 acc = make_float4(0.f, 0.f, 0.f, 0.f);
        #pragma unroll
        for (int k = 0; k < 4; ++k) {
            const int u = u_base + k * 8;
            const float w = __ldg(&w_out[u]);
            const float4 v = __ldg(W4 + (size_t)u * (ND / 4) + d4);
            acc.x = fmaf(w, v.x, acc.x); acc.y = fmaf(w, v.y, acc.y);
            acc.z = fmaf(w, v.z, acc.z); acc.w = fmaf(w, v.w, acc.w);
        }

        __shared__ float4 sp[256];
        sp[tid] = acc;
        __syncthreads();
        #pragma unroll
        for (int s = 128; s >= 32; s >>= 1) {
            if (tid < s) {
                float4 a = sp[tid], b = sp[tid + s];
                sp[tid] = make_float4(a.x + b.x, a.y + b.y, a.z + b.z, a.w + b.w);
            }
            __syncthreads();
        }
        if (tid < 32) {
            float* dst = is_h ? g_vh : g_vm;
            const float4 r = sp[tid];
            const int d = (dtile * 32 + tid) * 4;
            atomicAdd(&dst[d + 0], r.x); atomicAdd(&dst[d + 1], r.y);
            atomicAdd(&dst[d + 2], r.z); atomicAdd(&dst[d + 3], r.w);
        }
    } else {
        __shared__ float red[256];
        float acc = 0.f;
        for (int u = tid; u < NU; u += 256)
            acc = fmaf(w_out[u], b_h[u] + b_m[u], acc);
        red[tid] = acc;
        __syncthreads();
        for (int s = 128; s > 0; s >>= 1) {
            if (tid < s) red[tid] += red[tid + s];
            __syncthreads();
        }
        if (tid == 0) g_c = red[0] + b_out[0];
    }
}

// ---------------------------------------------------------------------------
// Kernel 2: per-token dual dot products (one warp per row, R9 math).
// PDL: preload all 8 x-float4 into registers BEFORE gridsync (no dependence
// on fold), then wait for fold, then load v_h/v_m to smem and compute.
// x read exactly once (streaming): 64 MiB.
// ---------------------------------------------------------------------------
__global__ void k_rowdots(const float* __restrict__ x) {
    const int tid = threadIdx.x;            // 256 threads = 8 warps
    const int warp = tid >> 5, lane = tid & 31;
    const int row = blockIdx.x * 8 + warp;  // 0 .. NB*NN-1
    const float4* x4 = reinterpret_cast<const float4*>(x) + (size_t)row * (ND / 4);

    float4 xr[8];
    #pragma unroll
    for (int k = 0; k < 8; ++k)
        xr[k] = __ldcs(&x4[k * 32 + lane]);

    cudaGridDependencySynchronize();        // fold results now visible
    cudaTriggerProgrammaticLaunchCompletion();

    __shared__ float4 svh[ND / 4];
    __shared__ float4 svm[ND / 4];
    svh[tid] = reinterpret_cast<const float4*>(g_vh)[tid];
    svm[tid] = reinterpret_cast<const float4*>(g_vm)[tid];
    __syncthreads();

    float ah = 0.f, am = 0.f;
    #pragma unroll
    for (int k = 0; k < 8; ++k) {
        const int idx = k * 32 + lane;
        const float4 xv = xr[k];
        const float4 vh = svh[idx];
        const float4 vm = svm[idx];
        ah = fmaf(xv.x, vh.x, ah); ah = fmaf(xv.y, vh.y, ah);
        ah = fmaf(xv.z, vh.z, ah); ah = fmaf(xv.w, vh.w, ah);
        am = fmaf(xv.x, vm.x, am); am = fmaf(xv.y, vm.y, am);
        am = fmaf(xv.z, vm.z, am); am = fmaf(xv.w, vm.w, am);
    }
    #pragma unroll
    for (int off = 16; off; off >>= 1) {
        ah += __shfl_xor_sync(0xffffffffu, ah, off);
        am += __shfl_xor_sync(0xffffffffu, am, off);
    }
    if (lane == 0) {
        g_sH[row] = ah + g_c;
        g_sM[row] = am;
    }
}

// ---------------------------------------------------------------------------
// Kernel 3: outer broadcast-add. scores[b,i,j] = sH[b,i] + sM[b,j].
// PDL-gridsync before reading sH/sM (hides launch gap). Grid-stride,
// 4 float4 per thread, fully coalesced. Tail re-zeros fold accumulators.
// ---------------------------------------------------------------------------
__global__ void k_outer(float* __restrict__ out) {
    const unsigned stride = 2048u * 512u;                 // 1,048,576 float4
    unsigned idx = blockIdx.x * 512u + threadIdx.x;
    const unsigned t0 = idx;

    cudaGridDependencySynchronize();        // rowdots results now visible

    #pragma unroll
    for (int t = 0; t < 4; ++t, idx += stride) {
        const unsigned j4 = idx & 255u;    // j/4, N/4 = 256
        const unsigned bi = idx >> 8;      // b*N + i
        const unsigned b  = bi >> 10;      // /N

        const float s = g_sH[bi];
        const float4 m = reinterpret_cast<const float4*>(g_sM)[(b << 8) + j4];
        reinterpret_cast<float4*>(out)[idx] =
            make_float4(s + m.x, s + m.y, s + m.z, s + m.w);
    }

    if (t0 < 512) {                        // re-zero accumulators (float4)
        const float4 z = make_float4(0.f, 0.f, 0.f, 0.f);
        if (t0 < 256) reinterpret_cast<float4*>(g_vh)[t0] = z;
        else          reinterpret_cast<float4*>(g_vm)[t0 - 256] = z;
    }
}

extern "C" void kernel_launch(void* const* d_in, const int* in_sizes, int n_in,
                              void* d_out, int out_size) {
    const float* x     = (const float*)d_in[0];
    const float* W_h   = (const float*)d_in[1];
    const float* b_h   = (const float*)d_in[2];
    const float* W_m   = (const float*)d_in[3];
    const float* b_m   = (const float*)d_in[4];
    const float* w_out = (const float*)d_in[5];
    const float* b_out = (const float*)d_in[6];
    float* out = (float*)d_out;

    // fold: plain launch (first in stream)
    k_fold<<<257, 256>>>(W_h, W_m, w_out, b_h, b_m, b_out);

    // rowdots + outer: PDL (may launch while predecessor still runs;
    // correctness via cudaGridDependencySynchronize inside).
    cudaLaunchAttribute attr[1];
    attr[0].id = cudaLaunchAttributeProgrammaticStreamSerialization;
    attr[0].val.programmaticStreamSerializationAllowed = 1;

    {
        cudaLaunchConfig_t cfg = {};
        cfg.gridDim  = dim3((NB * NN) / 8);
        cfg.blockDim = dim3(256);
        cfg.attrs    = attr;
        cfg.numAttrs = 1;
        cudaLaunchKernelEx(&cfg, k_rowdots, x);
    }
    {
        cudaLaunchConfig_t cfg = {};
        cfg.gridDim  = dim3(2048);
        cfg.blockDim = dim3(512);
        cfg.attrs    = attr;
        cfg.numAttrs = 1;
        cudaLaunchKernelEx(&cfg, k_outer, out);
    }
}